// round 1
// baseline (speedup 1.0000x reference)
#include <cuda_runtime.h>
#include <math.h>

// Problem constants
#define EMB    1024
#define HEADS  16
#define DHEAD  64
#define WINDOW 128
#define BATCH  2
#define SEQ    2048
#define MTOT   (BATCH * SEQ)   // 4096 rows

// ---------------------------------------------------------------------------
// Scratch (device globals — no allocation allowed in kernel_launch)
// ---------------------------------------------------------------------------
__device__ float g_q[MTOT * EMB];
__device__ float g_k[MTOT * EMB];
__device__ float g_v[MTOT * EMB];
__device__ float g_att[MTOT * EMB];

// ---------------------------------------------------------------------------
// SGEMM with bias: C[M x 1024] = X[M x 1024] @ W[1024 x 1024] + b
// Block tile 128x128, K-step 16, 256 threads, 8x8 per thread.
// blockIdx.z selects one of up to 3 (W, b, C) sets so QKV runs as one launch.
// ---------------------------------------------------------------------------
#define BM 128
#define BN 128
#define BK 16

__global__ __launch_bounds__(256) void gemm_bias_kernel(
    const float* __restrict__ X,
    const float* __restrict__ W0, const float* __restrict__ W1, const float* __restrict__ W2,
    const float* __restrict__ b0, const float* __restrict__ b1, const float* __restrict__ b2,
    float* __restrict__ C0, float* __restrict__ C1, float* __restrict__ C2)
{
    const int z = blockIdx.z;
    const float* __restrict__ W    = (z == 0) ? W0 : (z == 1) ? W1 : W2;
    const float* __restrict__ bias = (z == 0) ? b0 : (z == 1) ? b1 : b2;
    float* __restrict__ C          = (z == 0) ? C0 : (z == 1) ? C1 : C2;

    __shared__ float Xs[BK][BM + 4];   // [k][m], transposed on store
    __shared__ float Ws[BK][BN + 4];   // [k][n]

    const int tid = threadIdx.x;
    const int ty  = tid >> 4;          // 0..15
    const int tx  = tid & 15;          // 0..15
    const int m0  = blockIdx.y * BM;
    const int n0  = blockIdx.x * BN;

    float acc[8][8];
    #pragma unroll
    for (int i = 0; i < 8; i++)
        #pragma unroll
        for (int j = 0; j < 8; j++) acc[i][j] = 0.0f;

    for (int k0 = 0; k0 < EMB; k0 += BK) {
        // Load X tile (128 x 16), store transposed -> Xs[k][m]
        #pragma unroll
        for (int i = 0; i < 2; i++) {
            int idx = tid + i * 256;         // float4 index, 512 total
            int rm  = idx >> 2;              // 0..127
            int ck  = (idx & 3) * 4;         // 0,4,8,12
            float4 xv = *reinterpret_cast<const float4*>(
                &X[(size_t)(m0 + rm) * EMB + k0 + ck]);
            Xs[ck + 0][rm] = xv.x;
            Xs[ck + 1][rm] = xv.y;
            Xs[ck + 2][rm] = xv.z;
            Xs[ck + 3][rm] = xv.w;
        }
        // Load W tile (16 x 128), natural layout
        #pragma unroll
        for (int i = 0; i < 2; i++) {
            int idx = tid + i * 256;
            int rk  = idx >> 5;              // 0..15
            int cn  = (idx & 31) * 4;        // 0..124
            *reinterpret_cast<float4*>(&Ws[rk][cn]) =
                *reinterpret_cast<const float4*>(
                    &W[(size_t)(k0 + rk) * EMB + n0 + cn]);
        }
        __syncthreads();

        #pragma unroll
        for (int kk = 0; kk < BK; kk++) {
            float a[8], b[8];
            *reinterpret_cast<float4*>(a)     = *reinterpret_cast<float4*>(&Xs[kk][ty * 8]);
            *reinterpret_cast<float4*>(a + 4) = *reinterpret_cast<float4*>(&Xs[kk][ty * 8 + 4]);
            *reinterpret_cast<float4*>(b)     = *reinterpret_cast<float4*>(&Ws[kk][tx * 8]);
            *reinterpret_cast<float4*>(b + 4) = *reinterpret_cast<float4*>(&Ws[kk][tx * 8 + 4]);
            #pragma unroll
            for (int i = 0; i < 8; i++)
                #pragma unroll
                for (int j = 0; j < 8; j++)
                    acc[i][j] = fmaf(a[i], b[j], acc[i][j]);
        }
        __syncthreads();
    }

    // Epilogue: add bias, write out
    #pragma unroll
    for (int i = 0; i < 8; i++) {
        int m = m0 + ty * 8 + i;
        #pragma unroll
        for (int j = 0; j < 8; j += 4) {
            int n = n0 + tx * 8 + j;
            float4 o;
            o.x = acc[i][j + 0] + bias[n + 0];
            o.y = acc[i][j + 1] + bias[n + 1];
            o.z = acc[i][j + 2] + bias[n + 2];
            o.w = acc[i][j + 3] + bias[n + 3];
            *reinterpret_cast<float4*>(&C[(size_t)m * EMB + n]) = o;
        }
    }
}

// ---------------------------------------------------------------------------
// Windowed attention, flash-style online softmax.
// Grid: (SEQ/64, HEADS, BATCH). 256 threads = 16x16; each thread owns a
// 4(query) x 4(key or dim) register tile. Key window spans <= 5 tiles of 64
// (tile boundaries always multiples of 64 -> no partial tiles).
// smem: Qs/Ks/Vs/Ps each [64][68] fp32 = 69632 B (dynamic).
// ---------------------------------------------------------------------------
#define PITCH 68
#define SMEM_ATTN (4 * 64 * PITCH * 4)

__global__ __launch_bounds__(256) void attn_kernel(
    const float* __restrict__ Q, const float* __restrict__ K,
    const float* __restrict__ V, float* __restrict__ O)
{
    extern __shared__ float sm[];
    float* Qs = sm;                    // [64][PITCH]  (q, d)
    float* Ks = Qs + 64 * PITCH;       // [64][PITCH]  (k, d)
    float* Vs = Ks + 64 * PITCH;       // [64][PITCH]  (k, d)
    float* Ps = Vs + 64 * PITCH;       // [64][PITCH]  (q, k)

    const int tid = threadIdx.x;
    const int ty  = tid >> 4;          // query group 0..15
    const int tx  = tid & 15;          // key/dim group 0..15
    const int q0  = blockIdx.x * 64;
    const int h   = blockIdx.y;
    const int b   = blockIdx.z;

    const float scale = 1.0f / 32.0f;  // 1/sqrt(EMB)

    // Load Q tile (scaled)
    {
        const size_t qbase = ((size_t)(b * SEQ + q0)) * EMB + h * DHEAD;
        #pragma unroll
        for (int i = 0; i < 4; i++) {
            int idx = tid + i * 256;
            int qi  = idx >> 4;            // 0..63
            int d4  = (idx & 15) * 4;      // 0..60
            float4 v = *reinterpret_cast<const float4*>(&Q[qbase + (size_t)qi * EMB + d4]);
            v.x *= scale; v.y *= scale; v.z *= scale; v.w *= scale;
            *reinterpret_cast<float4*>(&Qs[qi * PITCH + d4]) = v;
        }
    }

    float mrow[4], lrow[4];
    float acc[4][4];
    #pragma unroll
    for (int qi = 0; qi < 4; qi++) {
        mrow[qi] = -3.0e38f;
        lrow[qi] = 0.0f;
        #pragma unroll
        for (int di = 0; di < 4; di++) acc[qi][di] = 0.0f;
    }

    int kstart = q0 - WINDOW; if (kstart < 0) kstart = 0;
    int kend   = q0 + 64 + WINDOW; if (kend > SEQ) kend = SEQ;

    for (int kt = kstart; kt < kend; kt += 64) {
        __syncthreads();   // previous tile's Ks/Vs/Ps fully consumed

        // Load K and V tiles
        {
            const size_t kbase = ((size_t)(b * SEQ + kt)) * EMB + h * DHEAD;
            #pragma unroll
            for (int i = 0; i < 4; i++) {
                int idx = tid + i * 256;
                int kk  = idx >> 4;
                int d4  = (idx & 15) * 4;
                float4 kv = *reinterpret_cast<const float4*>(&K[kbase + (size_t)kk * EMB + d4]);
                *reinterpret_cast<float4*>(&Ks[kk * PITCH + d4]) = kv;
                float4 vv = *reinterpret_cast<const float4*>(&V[kbase + (size_t)kk * EMB + d4]);
                *reinterpret_cast<float4*>(&Vs[kk * PITCH + d4]) = vv;
            }
        }
        __syncthreads();

        // S = Q K^T  (4x4 per thread)
        float s[4][4];
        #pragma unroll
        for (int qi = 0; qi < 4; qi++)
            #pragma unroll
            for (int kj = 0; kj < 4; kj++) s[qi][kj] = 0.0f;

        #pragma unroll
        for (int c = 0; c < DHEAD / 4; c++) {
            float qf[4][4], kf[4][4];
            #pragma unroll
            for (int qi = 0; qi < 4; qi++)
                *reinterpret_cast<float4*>(qf[qi]) =
                    *reinterpret_cast<float4*>(&Qs[(ty * 4 + qi) * PITCH + c * 4]);
            #pragma unroll
            for (int kj = 0; kj < 4; kj++)
                *reinterpret_cast<float4*>(kf[kj]) =
                    *reinterpret_cast<float4*>(&Ks[(tx * 4 + kj) * PITCH + c * 4]);
            #pragma unroll
            for (int u = 0; u < 4; u++)
                #pragma unroll
                for (int qi = 0; qi < 4; qi++)
                    #pragma unroll
                    for (int kj = 0; kj < 4; kj++)
                        s[qi][kj] = fmaf(qf[qi][u], kf[kj][u], s[qi][kj]);
        }

        // Window mask
        #pragma unroll
        for (int qi = 0; qi < 4; qi++) {
            int iq = q0 + ty * 4 + qi;
            #pragma unroll
            for (int kj = 0; kj < 4; kj++) {
                int jk = kt + tx * 4 + kj;
                int diff = iq - jk;
                if (diff < 0) diff = -diff;
                if (diff > WINDOW) s[qi][kj] = -1.0e30f;
            }
        }

        // Online softmax update; write P to smem
        #pragma unroll
        for (int qi = 0; qi < 4; qi++) {
            float tmax = fmaxf(fmaxf(s[qi][0], s[qi][1]), fmaxf(s[qi][2], s[qi][3]));
            #pragma unroll
            for (int o = 8; o >= 1; o >>= 1)
                tmax = fmaxf(tmax, __shfl_xor_sync(0xffffffffu, tmax, o));
            float newm = fmaxf(mrow[qi], tmax);
            float corr = __expf(mrow[qi] - newm);
            mrow[qi] = newm;
            lrow[qi] *= corr;
            #pragma unroll
            for (int di = 0; di < 4; di++) acc[qi][di] *= corr;
            float4 p;
            p.x = __expf(s[qi][0] - newm);
            p.y = __expf(s[qi][1] - newm);
            p.z = __expf(s[qi][2] - newm);
            p.w = __expf(s[qi][3] - newm);
            lrow[qi] += p.x + p.y + p.z + p.w;
            *reinterpret_cast<float4*>(&Ps[(ty * 4 + qi) * PITCH + tx * 4]) = p;
        }
        __syncthreads();

        // O += P @ V  (thread owns queries ty*4.., dims tx*4..)
        #pragma unroll
        for (int jc = 0; jc < 16; jc++) {
            float pv[4][4];
            #pragma unroll
            for (int qi = 0; qi < 4; qi++)
                *reinterpret_cast<float4*>(pv[qi]) =
                    *reinterpret_cast<float4*>(&Ps[(ty * 4 + qi) * PITCH + jc * 4]);
            #pragma unroll
            for (int u = 0; u < 4; u++) {
                float4 vv = *reinterpret_cast<float4*>(&Vs[(jc * 4 + u) * PITCH + tx * 4]);
                #pragma unroll
                for (int qi = 0; qi < 4; qi++) {
                    acc[qi][0] = fmaf(pv[qi][u], vv.x, acc[qi][0]);
                    acc[qi][1] = fmaf(pv[qi][u], vv.y, acc[qi][1]);
                    acc[qi][2] = fmaf(pv[qi][u], vv.z, acc[qi][2]);
                    acc[qi][3] = fmaf(pv[qi][u], vv.w, acc[qi][3]);
                }
            }
        }
    }

    // Final normalize + write
    #pragma unroll
    for (int qi = 0; qi < 4; qi++) {
        float l = lrow[qi];
        #pragma unroll
        for (int o = 8; o >= 1; o >>= 1)
            l += __shfl_xor_sync(0xffffffffu, l, o);
        float inv = 1.0f / l;
        int iq = q0 + ty * 4 + qi;
        float4 o4;
        o4.x = acc[qi][0] * inv;
        o4.y = acc[qi][1] * inv;
        o4.z = acc[qi][2] * inv;
        o4.w = acc[qi][3] * inv;
        *reinterpret_cast<float4*>(
            &O[((size_t)(b * SEQ + iq)) * EMB + h * DHEAD + tx * 4]) = o4;
    }
}

// ---------------------------------------------------------------------------
// Launch
// ---------------------------------------------------------------------------
extern "C" void kernel_launch(void* const* d_in, const int* in_sizes, int n_in,
                              void* d_out, int out_size)
{
    const float* x  = (const float*)d_in[0];
    const float* wq = (const float*)d_in[1];
    const float* bq = (const float*)d_in[2];
    const float* wk = (const float*)d_in[3];
    const float* bk = (const float*)d_in[4];
    const float* wv = (const float*)d_in[5];
    const float* bv = (const float*)d_in[6];
    const float* wo = (const float*)d_in[7];
    const float* bo = (const float*)d_in[8];
    float* out = (float*)d_out;

    float *gq, *gk, *gv, *ga;
    cudaGetSymbolAddress((void**)&gq, g_q);
    cudaGetSymbolAddress((void**)&gk, g_k);
    cudaGetSymbolAddress((void**)&gv, g_v);
    cudaGetSymbolAddress((void**)&ga, g_att);

    cudaFuncSetAttribute(attn_kernel,
                         cudaFuncAttributeMaxDynamicSharedMemorySize, SMEM_ATTN);

    // 1) QKV projections (one launch, z selects weight set)
    dim3 g1(EMB / BN, MTOT / BM, 3);
    gemm_bias_kernel<<<g1, 256>>>(x, wq, wk, wv, bq, bk, bv, gq, gk, gv);

    // 2) Windowed attention
    dim3 g2(SEQ / 64, HEADS, BATCH);
    attn_kernel<<<g2, 256, SMEM_ATTN>>>(gq, gk, gv, ga);

    // 3) Output projection
    dim3 g3(EMB / BN, MTOT / BM, 1);
    gemm_bias_kernel<<<g3, 256>>>(ga, wo, wo, wo, bo, bo, bo, out, out, out);
}

// round 3
// speedup vs baseline: 1.9029x; 1.9029x over previous
#include <cuda_runtime.h>
#include <cuda_fp16.h>
#include <math.h>

#define EMB    1024
#define HEADS  16
#define DHEAD  64
#define WINDOW 128
#define BATCH  2
#define SEQ    2048
#define MTOT   (BATCH * SEQ)

// ---------------------------------------------------------------------------
// Device-global scratch
// ---------------------------------------------------------------------------
__device__ float g_q[MTOT * EMB];
__device__ float g_k[MTOT * EMB];
__device__ float g_v[MTOT * EMB];
__device__ float g_att[MTOT * EMB];
__device__ __half g_xhi[MTOT * EMB];
__device__ __half g_xlo[MTOT * EMB];
__device__ __half g_ahi[MTOT * EMB];
__device__ __half g_alo[MTOT * EMB];
__device__ __half g_whi[4 * EMB * EMB];   // transposed: [n][k]
__device__ __half g_wlo[4 * EMB * EMB];

// ---------------------------------------------------------------------------
// PTX helpers (arch-neutral: cp.async / ldmatrix / mma.sync)
// ---------------------------------------------------------------------------
__device__ __forceinline__ unsigned s2u(const void* p) {
    unsigned a;
    asm("{ .reg .u64 t; cvta.to.shared.u64 t, %1; cvt.u32.u64 %0, t; }"
        : "=r"(a) : "l"(p));
    return a;
}
__device__ __forceinline__ void cp16(unsigned s, const void* g) {
    asm volatile("cp.async.cg.shared.global [%0], [%1], 16;" :: "r"(s), "l"(g));
}
#define CPA_COMMIT() asm volatile("cp.async.commit_group;" ::: "memory")
#define CPA_WAIT1()  asm volatile("cp.async.wait_group 1;" ::: "memory")

__device__ __forceinline__ void ldsm4(unsigned* r, unsigned a) {
    asm volatile("ldmatrix.sync.aligned.m8n8.x4.shared.b16 {%0,%1,%2,%3}, [%4];"
                 : "=r"(r[0]), "=r"(r[1]), "=r"(r[2]), "=r"(r[3]) : "r"(a));
}
__device__ __forceinline__ void ldsm2(unsigned* r, unsigned a) {
    asm volatile("ldmatrix.sync.aligned.m8n8.x2.shared.b16 {%0,%1}, [%2];"
                 : "=r"(r[0]), "=r"(r[1]) : "r"(a));
}
__device__ __forceinline__ void mma16816(float* c, const unsigned* a, const unsigned* b) {
    asm volatile(
        "mma.sync.aligned.m16n8k16.row.col.f32.f16.f16.f32 "
        "{%0,%1,%2,%3}, {%4,%5,%6,%7}, {%8,%9}, {%0,%1,%2,%3};"
        : "+f"(c[0]), "+f"(c[1]), "+f"(c[2]), "+f"(c[3])
        : "r"(a[0]), "r"(a[1]), "r"(a[2]), "r"(a[3]), "r"(b[0]), "r"(b[1]));
}

// ---------------------------------------------------------------------------
// Conversion kernels: fp32 -> (hi, lo) fp16 pair
// ---------------------------------------------------------------------------
__global__ void split_kernel(const float* __restrict__ src,
                             __half* __restrict__ hi,
                             __half* __restrict__ lo, int n4)
{
    int i = blockIdx.x * blockDim.x + threadIdx.x;
    if (i >= n4) return;
    float4 v = reinterpret_cast<const float4*>(src)[i];
    __half h0 = __float2half_rn(v.x);
    __half h1 = __float2half_rn(v.y);
    __half h2 = __float2half_rn(v.z);
    __half h3 = __float2half_rn(v.w);
    __half l0 = __float2half_rn(v.x - __half2float(h0));
    __half l1 = __float2half_rn(v.y - __half2float(h1));
    __half l2 = __float2half_rn(v.z - __half2float(h2));
    __half l3 = __float2half_rn(v.w - __half2float(h3));
    reinterpret_cast<__half2*>(hi)[2 * i + 0] = __halves2half2(h0, h1);
    reinterpret_cast<__half2*>(hi)[2 * i + 1] = __halves2half2(h2, h3);
    reinterpret_cast<__half2*>(lo)[2 * i + 0] = __halves2half2(l0, l1);
    reinterpret_cast<__half2*>(lo)[2 * i + 1] = __halves2half2(l2, l3);
}

// W[k][n] -> Wt[n][k], split hi/lo. grid (32,32,4), block (32,8)
__global__ void wsplit_kernel(const float* __restrict__ w0, const float* __restrict__ w1,
                              const float* __restrict__ w2, const float* __restrict__ w3,
                              __half* __restrict__ hi, __half* __restrict__ lo)
{
    __shared__ float t[32][33];
    int z = blockIdx.z;
    const float* W = (z == 0) ? w0 : (z == 1) ? w1 : (z == 2) ? w2 : w3;
    int n0 = blockIdx.x * 32, k0 = blockIdx.y * 32;
    #pragma unroll
    for (int i = 0; i < 4; i++) {
        int k = threadIdx.y + i * 8;
        t[k][threadIdx.x] = W[(size_t)(k0 + k) * EMB + n0 + threadIdx.x];
    }
    __syncthreads();
    size_t base = (size_t)z * EMB * EMB;
    #pragma unroll
    for (int i = 0; i < 4; i++) {
        int n = threadIdx.y + i * 8;
        float v = t[threadIdx.x][n];
        __half h = __float2half_rn(v);
        size_t o = base + (size_t)(n0 + n) * EMB + k0 + threadIdx.x;
        hi[o] = h;
        lo[o] = __float2half_rn(v - __half2float(h));
    }
}

// ---------------------------------------------------------------------------
// fp16x3 mma.sync GEMM: C[M x 1024] = A @ W + bias
// A hi/lo fp16 [M][K]; W hi/lo fp16 [N][K] (i.e. col-major B).
// CTA tile 128x128, BK=64, 2-stage cp.async pipeline, 8 warps (2x4), each
// warp owns 64x32 = 4x4 m16n8k16 tiles x 3 compensation passes.
// ---------------------------------------------------------------------------
#define BKC        64
#define TILE_HB    16384              // 128 rows x 128 bytes (64 halfs)
#define STAGE_HB   (4 * TILE_HB)      // Ahi, Alo, Bhi, Blo
#define NCHUNK     (EMB / BKC)        // 16
#define GEMM_SMEM  (2 * STAGE_HB)     // 131072

// swizzled smem byte offset for (row, 16B-segment)
__device__ __forceinline__ unsigned swz(int row, int seg) {
    return (unsigned)(row * 128 + ((seg ^ (row & 7)) << 4));
}

__device__ __forceinline__ void load_stage(
    unsigned st, int tid, int m0, int n0, int k0,
    const __half* Ah, const __half* Al,
    const __half* Bh, const __half* Bl)
{
    #pragma unroll
    for (int i = 0; i < 4; i++) {
        int idx = tid + i * 256;      // 0..1023
        int r   = idx >> 3;           // 0..127
        int s   = idx & 7;            // 16B segment
        unsigned sw = swz(r, s);
        size_t ga = (size_t)(m0 + r) * EMB + k0 + s * 8;
        size_t gb = (size_t)(n0 + r) * EMB + k0 + s * 8;
        cp16(st + sw,               Ah + ga);
        cp16(st + TILE_HB + sw,     Al + ga);
        cp16(st + 2 * TILE_HB + sw, Bh + gb);
        cp16(st + 3 * TILE_HB + sw, Bl + gb);
    }
}

__global__ __launch_bounds__(256) void gemm_mma(
    const __half* __restrict__ Ahi, const __half* __restrict__ Alo,
    const __half* __restrict__ Whi, const __half* __restrict__ Wlo,
    const float* __restrict__ b0, const float* __restrict__ b1, const float* __restrict__ b2,
    float* __restrict__ C0, float* __restrict__ C1, float* __restrict__ C2)
{
    extern __shared__ char smc[];
    const int z = blockIdx.z;
    const float* bias = (z == 0) ? b0 : (z == 1) ? b1 : b2;
    float* C          = (z == 0) ? C0 : (z == 1) ? C1 : C2;
    const __half* Bh = Whi + (size_t)z * EMB * EMB;
    const __half* Bl = Wlo + (size_t)z * EMB * EMB;
    const int m0  = blockIdx.y * 128;
    const int n0  = blockIdx.x * 128;
    const int tid = threadIdx.x;
    const int wid = tid >> 5, lane = tid & 31;
    const int wm  = wid & 1;          // 0..1 (64 rows each)
    const int wn  = wid >> 1;         // 0..3 (32 cols each)
    const unsigned sb = s2u(smc);

    float acc[4][4][4];
    #pragma unroll
    for (int mt = 0; mt < 4; mt++)
        #pragma unroll
        for (int nt = 0; nt < 4; nt++)
            #pragma unroll
            for (int e = 0; e < 4; e++) acc[mt][nt][e] = 0.0f;

    // Prologue
    load_stage(sb,            tid, m0, n0, 0,   Ahi, Alo, Bh, Bl);
    CPA_COMMIT();
    load_stage(sb + STAGE_HB, tid, m0, n0, BKC, Ahi, Alo, Bh, Bl);
    CPA_COMMIT();

    // Per-lane ldmatrix source rows
    const int arow = wm * 64 + (lane & 15);        // + mt*16
    const int brow = wn * 32 + (lane & 7);         // + nt*8
    const int aks  = lane >> 4;                    // extra k-segment for A
    const int bks  = (lane >> 3) & 1;              // extra k-segment for B

    for (int c = 0; c < NCHUNK; c++) {
        unsigned st = sb + (unsigned)(c & 1) * STAGE_HB;
        CPA_WAIT1();
        __syncthreads();

        #pragma unroll
        for (int k8 = 0; k8 < 8; k8 += 2) {       // 4 k-steps of 16
            unsigned bh[4][2], bl[4][2];
            #pragma unroll
            for (int nt = 0; nt < 4; nt++) {
                int rn = brow + nt * 8;
                unsigned off = swz(rn, k8 + bks);
                ldsm2(bh[nt], st + 2 * TILE_HB + off);
                ldsm2(bl[nt], st + 3 * TILE_HB + off);
            }
            #pragma unroll
            for (int mt = 0; mt < 4; mt++) {
                int rm = arow + mt * 16;
                unsigned off = swz(rm, k8 + aks);
                unsigned ah[4], al[4];
                ldsm4(ah, st + off);
                ldsm4(al, st + TILE_HB + off);
                #pragma unroll
                for (int nt = 0; nt < 4; nt++) {
                    mma16816(acc[mt][nt], ah, bh[nt]);
                    mma16816(acc[mt][nt], ah, bl[nt]);
                    mma16816(acc[mt][nt], al, bh[nt]);
                }
            }
        }
        __syncthreads();
        int cn = c + 2;
        if (cn < NCHUNK)
            load_stage(st, tid, m0, n0, cn * BKC, Ahi, Alo, Bh, Bl);
        CPA_COMMIT();
    }

    // Epilogue: registers -> gmem with bias (float2 stores)
    #pragma unroll
    for (int mt = 0; mt < 4; mt++) {
        int rbase = m0 + wm * 64 + mt * 16 + (lane >> 2);
        #pragma unroll
        for (int nt = 0; nt < 4; nt++) {
            int col = n0 + wn * 32 + nt * 8 + 2 * (lane & 3);
            float2 bv = *reinterpret_cast<const float2*>(&bias[col]);
            float2 o0, o1;
            o0.x = acc[mt][nt][0] + bv.x;
            o0.y = acc[mt][nt][1] + bv.y;
            o1.x = acc[mt][nt][2] + bv.x;
            o1.y = acc[mt][nt][3] + bv.y;
            *reinterpret_cast<float2*>(&C[(size_t)rbase * EMB + col]) = o0;
            *reinterpret_cast<float2*>(&C[(size_t)(rbase + 8) * EMB + col]) = o1;
        }
    }
}

// ---------------------------------------------------------------------------
// Windowed attention (fp32 flash-style, unchanged)
// ---------------------------------------------------------------------------
#define PITCH 68
#define SMEM_ATTN (4 * 64 * PITCH * 4)

__global__ __launch_bounds__(256) void attn_kernel(
    const float* __restrict__ Q, const float* __restrict__ K,
    const float* __restrict__ V, float* __restrict__ O)
{
    extern __shared__ float smf[];
    float* Qs = smf;
    float* Ks = Qs + 64 * PITCH;
    float* Vs = Ks + 64 * PITCH;
    float* Ps = Vs + 64 * PITCH;

    const int tid = threadIdx.x;
    const int ty  = tid >> 4;
    const int tx  = tid & 15;
    const int q0  = blockIdx.x * 64;
    const int h   = blockIdx.y;
    const int b   = blockIdx.z;
    const float scale = 1.0f / 32.0f;

    {
        const size_t qbase = ((size_t)(b * SEQ + q0)) * EMB + h * DHEAD;
        #pragma unroll
        for (int i = 0; i < 4; i++) {
            int idx = tid + i * 256;
            int qi  = idx >> 4;
            int d4  = (idx & 15) * 4;
            float4 v = *reinterpret_cast<const float4*>(&Q[qbase + (size_t)qi * EMB + d4]);
            v.x *= scale; v.y *= scale; v.z *= scale; v.w *= scale;
            *reinterpret_cast<float4*>(&Qs[qi * PITCH + d4]) = v;
        }
    }

    float mrow[4], lrow[4], acc[4][4];
    #pragma unroll
    for (int qi = 0; qi < 4; qi++) {
        mrow[qi] = -3.0e38f; lrow[qi] = 0.0f;
        #pragma unroll
        for (int di = 0; di < 4; di++) acc[qi][di] = 0.0f;
    }

    int kstart = q0 - WINDOW; if (kstart < 0) kstart = 0;
    int kend   = q0 + 64 + WINDOW; if (kend > SEQ) kend = SEQ;

    for (int kt = kstart; kt < kend; kt += 64) {
        __syncthreads();
        {
            const size_t kbase = ((size_t)(b * SEQ + kt)) * EMB + h * DHEAD;
            #pragma unroll
            for (int i = 0; i < 4; i++) {
                int idx = tid + i * 256;
                int kk  = idx >> 4;
                int d4  = (idx & 15) * 4;
                float4 kv = *reinterpret_cast<const float4*>(&K[kbase + (size_t)kk * EMB + d4]);
                *reinterpret_cast<float4*>(&Ks[kk * PITCH + d4]) = kv;
                float4 vv = *reinterpret_cast<const float4*>(&V[kbase + (size_t)kk * EMB + d4]);
                *reinterpret_cast<float4*>(&Vs[kk * PITCH + d4]) = vv;
            }
        }
        __syncthreads();

        float s[4][4];
        #pragma unroll
        for (int qi = 0; qi < 4; qi++)
            #pragma unroll
            for (int kj = 0; kj < 4; kj++) s[qi][kj] = 0.0f;

        #pragma unroll
        for (int c = 0; c < DHEAD / 4; c++) {
            float qf[4][4], kf[4][4];
            #pragma unroll
            for (int qi = 0; qi < 4; qi++)
                *reinterpret_cast<float4*>(qf[qi]) =
                    *reinterpret_cast<float4*>(&Qs[(ty * 4 + qi) * PITCH + c * 4]);
            #pragma unroll
            for (int kj = 0; kj < 4; kj++)
                *reinterpret_cast<float4*>(kf[kj]) =
                    *reinterpret_cast<float4*>(&Ks[(tx * 4 + kj) * PITCH + c * 4]);
            #pragma unroll
            for (int u = 0; u < 4; u++)
                #pragma unroll
                for (int qi = 0; qi < 4; qi++)
                    #pragma unroll
                    for (int kj = 0; kj < 4; kj++)
                        s[qi][kj] = fmaf(qf[qi][u], kf[kj][u], s[qi][kj]);
        }

        #pragma unroll
        for (int qi = 0; qi < 4; qi++) {
            int iq = q0 + ty * 4 + qi;
            #pragma unroll
            for (int kj = 0; kj < 4; kj++) {
                int jk = kt + tx * 4 + kj;
                int diff = iq - jk;
                if (diff < 0) diff = -diff;
                if (diff > WINDOW) s[qi][kj] = -1.0e30f;
            }
        }

        #pragma unroll
        for (int qi = 0; qi < 4; qi++) {
            float tmax = fmaxf(fmaxf(s[qi][0], s[qi][1]), fmaxf(s[qi][2], s[qi][3]));
            #pragma unroll
            for (int o = 8; o >= 1; o >>= 1)
                tmax = fmaxf(tmax, __shfl_xor_sync(0xffffffffu, tmax, o));
            float newm = fmaxf(mrow[qi], tmax);
            float corr = __expf(mrow[qi] - newm);
            mrow[qi] = newm;
            lrow[qi] *= corr;
            #pragma unroll
            for (int di = 0; di < 4; di++) acc[qi][di] *= corr;
            float4 p;
            p.x = __expf(s[qi][0] - newm);
            p.y = __expf(s[qi][1] - newm);
            p.z = __expf(s[qi][2] - newm);
            p.w = __expf(s[qi][3] - newm);
            lrow[qi] += p.x + p.y + p.z + p.w;
            *reinterpret_cast<float4*>(&Ps[(ty * 4 + qi) * PITCH + tx * 4]) = p;
        }
        __syncthreads();

        #pragma unroll
        for (int jc = 0; jc < 16; jc++) {
            float pv[4][4];
            #pragma unroll
            for (int qi = 0; qi < 4; qi++)
                *reinterpret_cast<float4*>(pv[qi]) =
                    *reinterpret_cast<float4*>(&Ps[(ty * 4 + qi) * PITCH + jc * 4]);
            #pragma unroll
            for (int u = 0; u < 4; u++) {
                float4 vv = *reinterpret_cast<float4*>(&Vs[(jc * 4 + u) * PITCH + tx * 4]);
                #pragma unroll
                for (int qi = 0; qi < 4; qi++) {
                    acc[qi][0] = fmaf(pv[qi][u], vv.x, acc[qi][0]);
                    acc[qi][1] = fmaf(pv[qi][u], vv.y, acc[qi][1]);
                    acc[qi][2] = fmaf(pv[qi][u], vv.z, acc[qi][2]);
                    acc[qi][3] = fmaf(pv[qi][u], vv.w, acc[qi][3]);
                }
            }
        }
    }

    #pragma unroll
    for (int qi = 0; qi < 4; qi++) {
        float l = lrow[qi];
        #pragma unroll
        for (int o = 8; o >= 1; o >>= 1)
            l += __shfl_xor_sync(0xffffffffu, l, o);
        float inv = 1.0f / l;
        int iq = q0 + ty * 4 + qi;
        float4 o4;
        o4.x = acc[qi][0] * inv;
        o4.y = acc[qi][1] * inv;
        o4.z = acc[qi][2] * inv;
        o4.w = acc[qi][3] * inv;
        *reinterpret_cast<float4*>(
            &O[((size_t)(b * SEQ + iq)) * EMB + h * DHEAD + tx * 4]) = o4;
    }
}

// ---------------------------------------------------------------------------
// Launch
// ---------------------------------------------------------------------------
extern "C" void kernel_launch(void* const* d_in, const int* in_sizes, int n_in,
                              void* d_out, int out_size)
{
    const float* x  = (const float*)d_in[0];
    const float* wq = (const float*)d_in[1];
    const float* bq = (const float*)d_in[2];
    const float* wk = (const float*)d_in[3];
    const float* bk = (const float*)d_in[4];
    const float* wv = (const float*)d_in[5];
    const float* bv = (const float*)d_in[6];
    const float* wo = (const float*)d_in[7];
    const float* bo = (const float*)d_in[8];
    float* out = (float*)d_out;

    float *gq, *gk, *gv, *ga;
    cudaGetSymbolAddress((void**)&gq, g_q);
    cudaGetSymbolAddress((void**)&gk, g_k);
    cudaGetSymbolAddress((void**)&gv, g_v);
    cudaGetSymbolAddress((void**)&ga, g_att);
    __half *xhi, *xlo, *ahi, *alo, *whi, *wlo;
    cudaGetSymbolAddress((void**)&xhi, g_xhi);
    cudaGetSymbolAddress((void**)&xlo, g_xlo);
    cudaGetSymbolAddress((void**)&ahi, g_ahi);
    cudaGetSymbolAddress((void**)&alo, g_alo);
    cudaGetSymbolAddress((void**)&whi, g_whi);
    cudaGetSymbolAddress((void**)&wlo, g_wlo);

    cudaFuncSetAttribute(attn_kernel, cudaFuncAttributeMaxDynamicSharedMemorySize, SMEM_ATTN);
    cudaFuncSetAttribute(gemm_mma, cudaFuncAttributeMaxDynamicSharedMemorySize, GEMM_SMEM);

    const int n4 = MTOT * EMB / 4;

    // 1) fp16 hi/lo splits of x and W (W transposed to [n][k])
    split_kernel<<<n4 / 256, 256>>>(x, xhi, xlo, n4);
    wsplit_kernel<<<dim3(32, 32, 4), dim3(32, 8)>>>(wq, wk, wv, wo, whi, wlo);

    // 2) QKV projections on tensor cores
    gemm_mma<<<dim3(8, 32, 3), 256, GEMM_SMEM>>>(xhi, xlo, whi, wlo,
                                                 bq, bk, bv, gq, gk, gv);

    // 3) Windowed attention
    attn_kernel<<<dim3(SEQ / 64, HEADS, BATCH), 256, SMEM_ATTN>>>(gq, gk, gv, ga);

    // 4) Split attention output, output projection on tensor cores
    split_kernel<<<n4 / 256, 256>>>(ga, ahi, alo, n4);
    gemm_mma<<<dim3(8, 32, 1), 256, GEMM_SMEM>>>(ahi, alo,
                                                 whi + (size_t)3 * EMB * EMB,
                                                 wlo + (size_t)3 * EMB * EMB,
                                                 bo, bo, bo, out, out, out);
}

// round 5
// speedup vs baseline: 2.9545x; 1.5526x over previous
#include <cuda_runtime.h>
#include <cuda_fp16.h>
#include <math.h>

#define EMB    1024
#define HEADS  16
#define DHEAD  64
#define WINDOW 128
#define BATCH  2
#define SEQ    2048
#define MTOT   (BATCH * SEQ)

// log2(e)/32 : folded into Q so softmax uses exp2
#define QSCALE 0.04508422f

// ---------------------------------------------------------------------------
// Device-global scratch (fp16 hi/lo pairs everywhere)
// ---------------------------------------------------------------------------
__device__ __half g_xhi[MTOT * EMB];
__device__ __half g_xlo[MTOT * EMB];
__device__ __half g_qhi[MTOT * EMB];
__device__ __half g_qlo[MTOT * EMB];
__device__ __half g_khi[MTOT * EMB];
__device__ __half g_klo[MTOT * EMB];
__device__ __half g_vhi[MTOT * EMB];
__device__ __half g_vlo[MTOT * EMB];
__device__ __half g_ahi[MTOT * EMB];
__device__ __half g_alo[MTOT * EMB];
__device__ __half g_whi[4 * EMB * EMB];   // transposed: [n][k]
__device__ __half g_wlo[4 * EMB * EMB];

// ---------------------------------------------------------------------------
// PTX helpers (arch-neutral: cp.async / ldmatrix / mma.sync)
// ---------------------------------------------------------------------------
__device__ __forceinline__ unsigned s2u(const void* p) {
    unsigned a;
    asm("{ .reg .u64 t; cvta.to.shared.u64 t, %1; cvt.u32.u64 %0, t; }"
        : "=r"(a) : "l"(p));
    return a;
}
__device__ __forceinline__ void cp16(unsigned s, const void* g) {
    asm volatile("cp.async.cg.shared.global [%0], [%1], 16;" :: "r"(s), "l"(g));
}
#define CPA_COMMIT() asm volatile("cp.async.commit_group;" ::: "memory")
#define CPA_WAIT1()  asm volatile("cp.async.wait_group 1;" ::: "memory")
#define CPA_WAIT2()  asm volatile("cp.async.wait_group 2;" ::: "memory")

__device__ __forceinline__ void ldsm4(unsigned* r, unsigned a) {
    asm volatile("ldmatrix.sync.aligned.m8n8.x4.shared.b16 {%0,%1,%2,%3}, [%4];"
                 : "=r"(r[0]), "=r"(r[1]), "=r"(r[2]), "=r"(r[3]) : "r"(a));
}
__device__ __forceinline__ void ldsm4t(unsigned* r, unsigned a) {
    asm volatile("ldmatrix.sync.aligned.m8n8.x4.trans.shared.b16 {%0,%1,%2,%3}, [%4];"
                 : "=r"(r[0]), "=r"(r[1]), "=r"(r[2]), "=r"(r[3]) : "r"(a));
}
__device__ __forceinline__ void ldsm2(unsigned* r, unsigned a) {
    asm volatile("ldmatrix.sync.aligned.m8n8.x2.shared.b16 {%0,%1}, [%2];"
                 : "=r"(r[0]), "=r"(r[1]) : "r"(a));
}
__device__ __forceinline__ void mma16816(float* c, const unsigned* a, const unsigned* b) {
    asm volatile(
        "mma.sync.aligned.m16n8k16.row.col.f32.f16.f16.f32 "
        "{%0,%1,%2,%3}, {%4,%5,%6,%7}, {%8,%9}, {%0,%1,%2,%3};"
        : "+f"(c[0]), "+f"(c[1]), "+f"(c[2]), "+f"(c[3])
        : "r"(a[0]), "r"(a[1]), "r"(a[2]), "r"(a[3]), "r"(b[0]), "r"(b[1]));
}

// swizzled smem byte offset for (row, 16B-segment): rows of 128 bytes
__device__ __forceinline__ unsigned swz(int row, int seg) {
    return (unsigned)(row * 128 + ((seg ^ (row & 7)) << 4));
}

// split two floats into packed hi half2 + lo half2
__device__ __forceinline__ unsigned packsplit(float a, float b, unsigned* lo) {
    __half ha = __float2half_rn(a), hb = __float2half_rn(b);
    __half la = __float2half_rn(a - __half2float(ha));
    __half lb = __float2half_rn(b - __half2float(hb));
    __half2 h2 = __halves2half2(ha, hb), l2 = __halves2half2(la, lb);
    *lo = *reinterpret_cast<unsigned*>(&l2);
    return *reinterpret_cast<unsigned*>(&h2);
}

// ---------------------------------------------------------------------------
// Conversion kernels
// ---------------------------------------------------------------------------
__global__ void split_kernel(const float* __restrict__ src,
                             __half* __restrict__ hi,
                             __half* __restrict__ lo, int n4)
{
    int i = blockIdx.x * blockDim.x + threadIdx.x;
    if (i >= n4) return;
    float4 v = reinterpret_cast<const float4*>(src)[i];
    unsigned l0, l1;
    unsigned h0 = packsplit(v.x, v.y, &l0);
    unsigned h1 = packsplit(v.z, v.w, &l1);
    reinterpret_cast<unsigned*>(hi)[2 * i + 0] = h0;
    reinterpret_cast<unsigned*>(hi)[2 * i + 1] = h1;
    reinterpret_cast<unsigned*>(lo)[2 * i + 0] = l0;
    reinterpret_cast<unsigned*>(lo)[2 * i + 1] = l1;
}

// W[k][n] -> Wt[n][k], split hi/lo. grid (32,32,4), block (32,8)
__global__ void wsplit_kernel(const float* __restrict__ w0, const float* __restrict__ w1,
                              const float* __restrict__ w2, const float* __restrict__ w3,
                              __half* __restrict__ hi, __half* __restrict__ lo)
{
    __shared__ float t[32][33];
    int z = blockIdx.z;
    const float* W = (z == 0) ? w0 : (z == 1) ? w1 : (z == 2) ? w2 : w3;
    int n0 = blockIdx.x * 32, k0 = blockIdx.y * 32;
    #pragma unroll
    for (int i = 0; i < 4; i++) {
        int k = threadIdx.y + i * 8;
        t[k][threadIdx.x] = W[(size_t)(k0 + k) * EMB + n0 + threadIdx.x];
    }
    __syncthreads();
    size_t base = (size_t)z * EMB * EMB;
    #pragma unroll
    for (int i = 0; i < 4; i++) {
        int n = threadIdx.y + i * 8;
        float v = t[threadIdx.x][n];
        __half h = __float2half_rn(v);
        size_t o = base + (size_t)(n0 + n) * EMB + k0 + threadIdx.x;
        hi[o] = h;
        lo[o] = __float2half_rn(v - __half2float(h));
    }
}

// ---------------------------------------------------------------------------
// fp16x3 mma.sync GEMM. SPLIT=true: writes (hi,lo) fp16 with per-z scale.
// SPLIT=false: writes fp32.
// ---------------------------------------------------------------------------
#define BKC        64
#define TILE_HB    16384
#define STAGE_HB   (4 * TILE_HB)
#define NCHUNK     (EMB / BKC)
#define GEMM_SMEM  (2 * STAGE_HB)

__device__ __forceinline__ void load_stage(
    unsigned st, int tid, int m0, int n0, int k0,
    const __half* Ah, const __half* Al,
    const __half* Bh, const __half* Bl)
{
    #pragma unroll
    for (int i = 0; i < 4; i++) {
        int idx = tid + i * 256;
        int r   = idx >> 3;
        int s   = idx & 7;
        unsigned sw = swz(r, s);
        size_t ga = (size_t)(m0 + r) * EMB + k0 + s * 8;
        size_t gb = (size_t)(n0 + r) * EMB + k0 + s * 8;
        cp16(st + sw,               Ah + ga);
        cp16(st + TILE_HB + sw,     Al + ga);
        cp16(st + 2 * TILE_HB + sw, Bh + gb);
        cp16(st + 3 * TILE_HB + sw, Bl + gb);
    }
}

template<bool SPLIT>
__global__ __launch_bounds__(256) void gemm_mma(
    const __half* __restrict__ Ahi, const __half* __restrict__ Alo,
    const __half* __restrict__ Whi, const __half* __restrict__ Wlo,
    const float* __restrict__ b0, const float* __restrict__ b1, const float* __restrict__ b2,
    float* __restrict__ Cf0, float* __restrict__ Cf1, float* __restrict__ Cf2,
    __half* __restrict__ Ch0, __half* __restrict__ Cl0,
    __half* __restrict__ Ch1, __half* __restrict__ Cl1,
    __half* __restrict__ Ch2, __half* __restrict__ Cl2,
    float s0, float s1, float s2)
{
    extern __shared__ char smc[];
    const int z = blockIdx.z;
    const float* bias = (z == 0) ? b0 : (z == 1) ? b1 : b2;
    float* Cf  = (z == 0) ? Cf0 : (z == 1) ? Cf1 : Cf2;
    __half* Ch = (z == 0) ? Ch0 : (z == 1) ? Ch1 : Ch2;
    __half* Cl = (z == 0) ? Cl0 : (z == 1) ? Cl1 : Cl2;
    float scale = (z == 0) ? s0 : (z == 1) ? s1 : s2;
    const __half* Bh = Whi + (size_t)z * EMB * EMB;
    const __half* Bl = Wlo + (size_t)z * EMB * EMB;
    const int m0  = blockIdx.y * 128;
    const int n0  = blockIdx.x * 128;
    const int tid = threadIdx.x;
    const int wid = tid >> 5, lane = tid & 31;
    const int wm  = wid & 1;
    const int wn  = wid >> 1;
    const unsigned sb = s2u(smc);

    float acc[4][4][4];
    #pragma unroll
    for (int mt = 0; mt < 4; mt++)
        #pragma unroll
        for (int nt = 0; nt < 4; nt++)
            #pragma unroll
            for (int e = 0; e < 4; e++) acc[mt][nt][e] = 0.0f;

    load_stage(sb,            tid, m0, n0, 0,   Ahi, Alo, Bh, Bl);
    CPA_COMMIT();
    load_stage(sb + STAGE_HB, tid, m0, n0, BKC, Ahi, Alo, Bh, Bl);
    CPA_COMMIT();

    const int arow = wm * 64 + (lane & 15);
    const int brow = wn * 32 + (lane & 7);
    const int aks  = lane >> 4;
    const int bks  = (lane >> 3) & 1;

    for (int c = 0; c < NCHUNK; c++) {
        unsigned st = sb + (unsigned)(c & 1) * STAGE_HB;
        CPA_WAIT1();
        __syncthreads();

        #pragma unroll
        for (int k8 = 0; k8 < 8; k8 += 2) {
            unsigned bh[4][2], bl[4][2];
            #pragma unroll
            for (int nt = 0; nt < 4; nt++) {
                unsigned off = swz(brow + nt * 8, k8 + bks);
                ldsm2(bh[nt], st + 2 * TILE_HB + off);
                ldsm2(bl[nt], st + 3 * TILE_HB + off);
            }
            #pragma unroll
            for (int mt = 0; mt < 4; mt++) {
                unsigned off = swz(arow + mt * 16, k8 + aks);
                unsigned ah[4], al[4];
                ldsm4(ah, st + off);
                ldsm4(al, st + TILE_HB + off);
                #pragma unroll
                for (int nt = 0; nt < 4; nt++) {
                    mma16816(acc[mt][nt], ah, bh[nt]);
                    mma16816(acc[mt][nt], ah, bl[nt]);
                    mma16816(acc[mt][nt], al, bh[nt]);
                }
            }
        }
        __syncthreads();
        int cn = c + 2;
        if (cn < NCHUNK)
            load_stage(st, tid, m0, n0, cn * BKC, Ahi, Alo, Bh, Bl);
        CPA_COMMIT();
    }

    #pragma unroll
    for (int mt = 0; mt < 4; mt++) {
        int rbase = m0 + wm * 64 + mt * 16 + (lane >> 2);
        #pragma unroll
        for (int nt = 0; nt < 4; nt++) {
            int col = n0 + wn * 32 + nt * 8 + 2 * (lane & 3);
            float2 bv = *reinterpret_cast<const float2*>(&bias[col]);
            float v0 = acc[mt][nt][0] + bv.x;
            float v1 = acc[mt][nt][1] + bv.y;
            float v2 = acc[mt][nt][2] + bv.x;
            float v3 = acc[mt][nt][3] + bv.y;
            if (SPLIT) {
                v0 *= scale; v1 *= scale; v2 *= scale; v3 *= scale;
                unsigned lo0, lo1;
                unsigned h0 = packsplit(v0, v1, &lo0);
                unsigned h1 = packsplit(v2, v3, &lo1);
                *reinterpret_cast<unsigned*>(&Ch[(size_t)rbase * EMB + col]) = h0;
                *reinterpret_cast<unsigned*>(&Cl[(size_t)rbase * EMB + col]) = lo0;
                *reinterpret_cast<unsigned*>(&Ch[(size_t)(rbase + 8) * EMB + col]) = h1;
                *reinterpret_cast<unsigned*>(&Cl[(size_t)(rbase + 8) * EMB + col]) = lo1;
            } else {
                float2 o0 = {v0, v1}, o1 = {v2, v3};
                *reinterpret_cast<float2*>(&Cf[(size_t)rbase * EMB + col]) = o0;
                *reinterpret_cast<float2*>(&Cf[(size_t)(rbase + 8) * EMB + col]) = o1;
            }
        }
    }
}

// ---------------------------------------------------------------------------
// Tensor-core windowed attention (fp16 compensated, flash-style)
// Grid (SEQ/64, HEADS, BATCH), 128 threads = 4 warps, warp owns 16 queries.
// Key tiles of 64; 3-5 tiles per CTA. Double-buffered cp.async K/V hi/lo.
// Q pre-scaled by log2(e)/32 -> exp2 softmax.
// ---------------------------------------------------------------------------
#define KV_TILE   8192                 // 64 rows x 128 B
#define KV_STAGE  (4 * KV_TILE)        // Khi, Klo, Vhi, Vlo
#define ATTN_SMEM (2 * KV_TILE + 2 * KV_STAGE)   // Q hi/lo + 2 stages = 81920

__device__ __forceinline__ void load_kv(
    unsigned st, int tid, int b, int kt, int h,
    const __half* Kh, const __half* Kl, const __half* Vh, const __half* Vl)
{
    #pragma unroll
    for (int i = 0; i < 4; i++) {
        int idx = tid + i * 128;
        int r = idx >> 3, s = idx & 7;
        unsigned sw = swz(r, s);
        size_t g = (size_t)(b * SEQ + kt + r) * EMB + h * DHEAD + s * 8;
        cp16(st + sw,               Kh + g);
        cp16(st + KV_TILE + sw,     Kl + g);
        cp16(st + 2 * KV_TILE + sw, Vh + g);
        cp16(st + 3 * KV_TILE + sw, Vl + g);
    }
}

__global__ __launch_bounds__(128) void attn_mma(
    const __half* __restrict__ Qh, const __half* __restrict__ Ql,
    const __half* __restrict__ Kh, const __half* __restrict__ Kl,
    const __half* __restrict__ Vh, const __half* __restrict__ Vl,
    __half* __restrict__ Ohi, __half* __restrict__ Olo)
{
    extern __shared__ char smb[];
    const unsigned sb = s2u(smb);
    const unsigned Qhi_s = sb;
    const unsigned Qlo_s = sb + KV_TILE;
    const unsigned st0   = sb + 2 * KV_TILE;

    const int tid = threadIdx.x, wid = tid >> 5, lane = tid & 31;
    const int q0 = blockIdx.x * 64, h = blockIdx.y, b = blockIdx.z;

    int kstart = q0 - 128; if (kstart < 0) kstart = 0;
    int kend   = q0 + 192; if (kend > SEQ) kend = SEQ;
    const int ntiles = (kend - kstart) >> 6;   // 3..5

    // Prologue: Q tile + first two K/V stages
    {
        const size_t qg = (size_t)(b * SEQ + q0) * EMB + h * DHEAD;
        #pragma unroll
        for (int i = 0; i < 4; i++) {
            int idx = tid + i * 128;
            int r = idx >> 3, s = idx & 7;
            unsigned sw = swz(r, s);
            size_t g = qg + (size_t)r * EMB + s * 8;
            cp16(Qhi_s + sw, Qh + g);
            cp16(Qlo_s + sw, Ql + g);
        }
    }
    CPA_COMMIT();
    load_kv(st0,            tid, b, kstart,      h, Kh, Kl, Vh, Vl);
    CPA_COMMIT();
    load_kv(st0 + KV_STAGE, tid, b, kstart + 64, h, Kh, Kl, Vh, Vl);
    CPA_COMMIT();

    CPA_WAIT2();
    __syncthreads();

    // Q fragments into registers
    unsigned qfh[4][4], qfl[4][4];
    {
        int qrow = wid * 16 + (lane & 15);
        int aks  = lane >> 4;
        #pragma unroll
        for (int kc = 0; kc < 4; kc++) {
            unsigned off = swz(qrow, kc * 2 + aks);
            ldsm4(qfh[kc], Qhi_s + off);
            ldsm4(qfl[kc], Qlo_s + off);
        }
    }

    float o[8][4];
    #pragma unroll
    for (int i = 0; i < 8; i++)
        #pragma unroll
        for (int e = 0; e < 4; e++) o[i][e] = 0.0f;
    float m0 = -1e30f, m1 = -1e30f, l0 = 0.0f, l1 = 0.0f;

    for (int t = 0; t < ntiles; t++) {
        unsigned st = st0 + (unsigned)(t & 1) * KV_STAGE;
        CPA_WAIT1();
        __syncthreads();
        const int kt = kstart + t * 64;

        // ---- S = Q K^T (3 compensated passes) ----
        float s[8][4];
        #pragma unroll
        for (int i = 0; i < 8; i++)
            #pragma unroll
            for (int e = 0; e < 4; e++) s[i][e] = 0.0f;

        #pragma unroll
        for (int np = 0; np < 4; np++) {
            int krow = np * 16 + ((lane >> 4) << 3) + (lane & 7);
            #pragma unroll
            for (int kc = 0; kc < 4; kc++) {
                unsigned off = swz(krow, kc * 2 + ((lane >> 3) & 1));
                unsigned kb[4], kbl[4];
                ldsm4(kb,  st + off);
                ldsm4(kbl, st + KV_TILE + off);
                mma16816(s[2 * np],     qfh[kc], kb);
                mma16816(s[2 * np],     qfh[kc], kbl);
                mma16816(s[2 * np],     qfl[kc], kb);
                mma16816(s[2 * np + 1], qfh[kc], kb + 2);
                mma16816(s[2 * np + 1], qfh[kc], kbl + 2);
                mma16816(s[2 * np + 1], qfl[kc], kb + 2);
            }
        }

        // ---- window mask (only edge tiles) ----
        if (kt == q0 + 128 || kt + 128 == q0) {
            int iqb = q0 + wid * 16 + (lane >> 2);
            int jkb = kt + 2 * (lane & 3);
            #pragma unroll
            for (int nt = 0; nt < 8; nt++)
                #pragma unroll
                for (int e = 0; e < 4; e++) {
                    int iq = iqb + ((e >> 1) << 3);
                    int jk = jkb + nt * 8 + (e & 1);
                    int d = iq - jk; if (d < 0) d = -d;
                    if (d > WINDOW) s[nt][e] = -1e30f;
                }
        }

        // ---- online softmax ----
        float mx0 = -1e30f, mx1 = -1e30f;
        #pragma unroll
        for (int nt = 0; nt < 8; nt++) {
            mx0 = fmaxf(mx0, fmaxf(s[nt][0], s[nt][1]));
            mx1 = fmaxf(mx1, fmaxf(s[nt][2], s[nt][3]));
        }
        mx0 = fmaxf(mx0, __shfl_xor_sync(0xffffffffu, mx0, 1));
        mx0 = fmaxf(mx0, __shfl_xor_sync(0xffffffffu, mx0, 2));
        mx1 = fmaxf(mx1, __shfl_xor_sync(0xffffffffu, mx1, 1));
        mx1 = fmaxf(mx1, __shfl_xor_sync(0xffffffffu, mx1, 2));
        float nm0 = fmaxf(m0, mx0), nm1 = fmaxf(m1, mx1);
        float c0 = exp2f(m0 - nm0), c1 = exp2f(m1 - nm1);
        m0 = nm0; m1 = nm1;
        l0 *= c0;  l1 *= c1;
        #pragma unroll
        for (int nt = 0; nt < 8; nt++) {
            o[nt][0] *= c0; o[nt][1] *= c0;
            o[nt][2] *= c1; o[nt][3] *= c1;
        }

        // p = exp2(s - m), split hi/lo, pack straight into A-fragments
        unsigned pha[4][4], pla[4][4];
        #pragma unroll
        for (int np = 0; np < 4; np++) {
            float pe0 = exp2f(s[2 * np][0] - m0), pe1 = exp2f(s[2 * np][1] - m0);
            float pe2 = exp2f(s[2 * np][2] - m1), pe3 = exp2f(s[2 * np][3] - m1);
            float po0 = exp2f(s[2 * np + 1][0] - m0), po1 = exp2f(s[2 * np + 1][1] - m0);
            float po2 = exp2f(s[2 * np + 1][2] - m1), po3 = exp2f(s[2 * np + 1][3] - m1);
            l0 += pe0 + pe1 + po0 + po1;
            l1 += pe2 + pe3 + po2 + po3;
            pha[np][0] = packsplit(pe0, pe1, &pla[np][0]);
            pha[np][1] = packsplit(pe2, pe3, &pla[np][1]);
            pha[np][2] = packsplit(po0, po1, &pla[np][2]);
            pha[np][3] = packsplit(po2, po3, &pla[np][3]);
        }

        // ---- O += P V (3 compensated passes, V via trans ldmatrix) ----
        #pragma unroll
        for (int kc2 = 0; kc2 < 4; kc2++) {
            int vrow = kc2 * 16 + (lane & 15);
            #pragma unroll
            for (int dp = 0; dp < 4; dp++) {
                unsigned off = swz(vrow, dp * 2 + (lane >> 4));
                unsigned vb[4], vbl[4];
                ldsm4t(vb,  st + 2 * KV_TILE + off);
                ldsm4t(vbl, st + 3 * KV_TILE + off);
                mma16816(o[2 * dp],     pha[kc2], vb);
                mma16816(o[2 * dp],     pha[kc2], vbl);
                mma16816(o[2 * dp],     pla[kc2], vb);
                mma16816(o[2 * dp + 1], pha[kc2], vb + 2);
                mma16816(o[2 * dp + 1], pha[kc2], vbl + 2);
                mma16816(o[2 * dp + 1], pla[kc2], vb + 2);
            }
        }

        __syncthreads();
        int tn = t + 2;
        if (tn < ntiles)
            load_kv(st, tid, b, kstart + tn * 64, h, Kh, Kl, Vh, Vl);
        CPA_COMMIT();
    }

    // final normalize + hi/lo split write
    l0 += __shfl_xor_sync(0xffffffffu, l0, 1);
    l0 += __shfl_xor_sync(0xffffffffu, l0, 2);
    l1 += __shfl_xor_sync(0xffffffffu, l1, 1);
    l1 += __shfl_xor_sync(0xffffffffu, l1, 2);
    float inv0 = 1.0f / l0, inv1 = 1.0f / l1;

    int row0 = q0 + wid * 16 + (lane >> 2);
    size_t t0 = (size_t)(b * SEQ + row0) * EMB + h * DHEAD;
    size_t t1 = t0 + (size_t)8 * EMB;
    #pragma unroll
    for (int nt = 0; nt < 8; nt++) {
        int col = nt * 8 + 2 * (lane & 3);
        unsigned lo0, lo1;
        unsigned h0 = packsplit(o[nt][0] * inv0, o[nt][1] * inv0, &lo0);
        unsigned h1 = packsplit(o[nt][2] * inv1, o[nt][3] * inv1, &lo1);
        *reinterpret_cast<unsigned*>(&Ohi[t0 + col]) = h0;
        *reinterpret_cast<unsigned*>(&Olo[t0 + col]) = lo0;
        *reinterpret_cast<unsigned*>(&Ohi[t1 + col]) = h1;
        *reinterpret_cast<unsigned*>(&Olo[t1 + col]) = lo1;
    }
}

// ---------------------------------------------------------------------------
// Launch
// ---------------------------------------------------------------------------
extern "C" void kernel_launch(void* const* d_in, const int* in_sizes, int n_in,
                              void* d_out, int out_size)
{
    const float* x  = (const float*)d_in[0];
    const float* wq = (const float*)d_in[1];
    const float* bq = (const float*)d_in[2];
    const float* wk = (const float*)d_in[3];
    const float* bk = (const float*)d_in[4];
    const float* wv = (const float*)d_in[5];
    const float* bv = (const float*)d_in[6];
    const float* wo = (const float*)d_in[7];
    const float* bo = (const float*)d_in[8];
    float* out = (float*)d_out;

    __half *xhi, *xlo, *qhi, *qlo, *khi, *klo, *vhi, *vlo, *ahi, *alo, *whi, *wlo;
    cudaGetSymbolAddress((void**)&xhi, g_xhi);
    cudaGetSymbolAddress((void**)&xlo, g_xlo);
    cudaGetSymbolAddress((void**)&qhi, g_qhi);
    cudaGetSymbolAddress((void**)&qlo, g_qlo);
    cudaGetSymbolAddress((void**)&khi, g_khi);
    cudaGetSymbolAddress((void**)&klo, g_klo);
    cudaGetSymbolAddress((void**)&vhi, g_vhi);
    cudaGetSymbolAddress((void**)&vlo, g_vlo);
    cudaGetSymbolAddress((void**)&ahi, g_ahi);
    cudaGetSymbolAddress((void**)&alo, g_alo);
    cudaGetSymbolAddress((void**)&whi, g_whi);
    cudaGetSymbolAddress((void**)&wlo, g_wlo);

    cudaFuncSetAttribute(gemm_mma<true>,  cudaFuncAttributeMaxDynamicSharedMemorySize, GEMM_SMEM);
    cudaFuncSetAttribute(gemm_mma<false>, cudaFuncAttributeMaxDynamicSharedMemorySize, GEMM_SMEM);
    cudaFuncSetAttribute(attn_mma, cudaFuncAttributeMaxDynamicSharedMemorySize, ATTN_SMEM);

    const int n4 = MTOT * EMB / 4;

    // 1) splits
    split_kernel<<<n4 / 256, 256>>>(x, xhi, xlo, n4);
    wsplit_kernel<<<dim3(32, 32, 4), dim3(32, 8)>>>(wq, wk, wv, wo, whi, wlo);

    // 2) QKV projections -> hi/lo fp16 (Q pre-scaled by log2e/32)
    gemm_mma<true><<<dim3(8, 32, 3), 256, GEMM_SMEM>>>(
        xhi, xlo, whi, wlo, bq, bk, bv,
        nullptr, nullptr, nullptr,
        qhi, qlo, khi, klo, vhi, vlo,
        QSCALE, 1.0f, 1.0f);

    // 3) Tensor-core windowed attention -> hi/lo fp16
    attn_mma<<<dim3(SEQ / 64, HEADS, BATCH), 128, ATTN_SMEM>>>(
        qhi, qlo, khi, klo, vhi, vlo, ahi, alo);

    // 4) Output projection -> fp32
    gemm_mma<false><<<dim3(8, 32, 1), 256, GEMM_SMEM>>>(
        ahi, alo, whi + (size_t)3 * EMB * EMB, wlo + (size_t)3 * EMB * EMB,
        bo, bo, bo,
        out, out, out,
        nullptr, nullptr, nullptr, nullptr, nullptr, nullptr,
        1.0f, 1.0f, 1.0f);
}

// round 6
// speedup vs baseline: 4.1448x; 1.4029x over previous
#include <cuda_runtime.h>
#include <cuda_fp16.h>
#include <math.h>

#define EMB    1024
#define HEADS  16
#define DHEAD  64
#define WINDOW 128
#define BATCH  2
#define SEQ    2048
#define MTOT   (BATCH * SEQ)

// log2(e)/32 : folded into Q so softmax uses exp2
#define QSCALE 0.04508422f

// ---------------------------------------------------------------------------
// Device-global scratch
// ---------------------------------------------------------------------------
__device__ __half g_xhi[MTOT * EMB];
__device__ __half g_qhi[MTOT * EMB];
__device__ __half g_qlo[MTOT * EMB];   // written by GEMM epilogue, unused
__device__ __half g_khi[MTOT * EMB];
__device__ __half g_klo[MTOT * EMB];
__device__ __half g_vhi[MTOT * EMB];
__device__ __half g_vlo[MTOT * EMB];
__device__ __half g_ahi[MTOT * EMB];
__device__ __half g_whi[4 * EMB * EMB];   // transposed: [n][k]
__device__ __half g_wlo[4 * EMB * EMB];

// ---------------------------------------------------------------------------
// PTX helpers
// ---------------------------------------------------------------------------
__device__ __forceinline__ unsigned s2u(const void* p) {
    unsigned a;
    asm("{ .reg .u64 t; cvta.to.shared.u64 t, %1; cvt.u32.u64 %0, t; }"
        : "=r"(a) : "l"(p));
    return a;
}
__device__ __forceinline__ void cp16(unsigned s, const void* g) {
    asm volatile("cp.async.cg.shared.global [%0], [%1], 16;" :: "r"(s), "l"(g));
}
#define CPA_COMMIT() asm volatile("cp.async.commit_group;" ::: "memory")
#define CPA_WAIT1()  asm volatile("cp.async.wait_group 1;" ::: "memory")
#define CPA_WAIT2()  asm volatile("cp.async.wait_group 2;" ::: "memory")

__device__ __forceinline__ void ldsm4(unsigned* r, unsigned a) {
    asm volatile("ldmatrix.sync.aligned.m8n8.x4.shared.b16 {%0,%1,%2,%3}, [%4];"
                 : "=r"(r[0]), "=r"(r[1]), "=r"(r[2]), "=r"(r[3]) : "r"(a));
}
__device__ __forceinline__ void ldsm4t(unsigned* r, unsigned a) {
    asm volatile("ldmatrix.sync.aligned.m8n8.x4.trans.shared.b16 {%0,%1,%2,%3}, [%4];"
                 : "=r"(r[0]), "=r"(r[1]), "=r"(r[2]), "=r"(r[3]) : "r"(a));
}
__device__ __forceinline__ void mma16816(float* c, const unsigned* a, const unsigned* b) {
    asm volatile(
        "mma.sync.aligned.m16n8k16.row.col.f32.f16.f16.f32 "
        "{%0,%1,%2,%3}, {%4,%5,%6,%7}, {%8,%9}, {%0,%1,%2,%3};"
        : "+f"(c[0]), "+f"(c[1]), "+f"(c[2]), "+f"(c[3])
        : "r"(a[0]), "r"(a[1]), "r"(a[2]), "r"(a[3]), "r"(b[0]), "r"(b[1]));
}

// swizzled smem byte offset for (row, 16B-segment): rows of 128 bytes
__device__ __forceinline__ unsigned swz(int row, int seg) {
    return (unsigned)(row * 128 + ((seg ^ (row & 7)) << 4));
}

// split two floats into packed hi half2 + lo half2
__device__ __forceinline__ unsigned packsplit(float a, float b, unsigned* lo) {
    __half ha = __float2half_rn(a), hb = __float2half_rn(b);
    __half la = __float2half_rn(a - __half2float(ha));
    __half lb = __float2half_rn(b - __half2float(hb));
    __half2 h2 = __halves2half2(ha, hb), l2 = __halves2half2(la, lb);
    *lo = *reinterpret_cast<unsigned*>(&l2);
    return *reinterpret_cast<unsigned*>(&h2);
}
__device__ __forceinline__ unsigned pack2h(float a, float b) {
    __half2 h = __floats2half2_rn(a, b);
    return *reinterpret_cast<unsigned*>(&h);
}

// ---------------------------------------------------------------------------
// Conversion kernels
// ---------------------------------------------------------------------------
__global__ void tohalf_kernel(const float* __restrict__ src,
                              __half* __restrict__ dst, int n4)
{
    int i = blockIdx.x * blockDim.x + threadIdx.x;
    if (i >= n4) return;
    float4 v = reinterpret_cast<const float4*>(src)[i];
    reinterpret_cast<unsigned*>(dst)[2 * i + 0] = pack2h(v.x, v.y);
    reinterpret_cast<unsigned*>(dst)[2 * i + 1] = pack2h(v.z, v.w);
}

// W[k][n] -> Wt[n][k], split hi/lo. grid (32,32,4), block (32,8)
__global__ void wsplit_kernel(const float* __restrict__ w0, const float* __restrict__ w1,
                              const float* __restrict__ w2, const float* __restrict__ w3,
                              __half* __restrict__ hi, __half* __restrict__ lo)
{
    __shared__ float t[32][33];
    int z = blockIdx.z;
    const float* W = (z == 0) ? w0 : (z == 1) ? w1 : (z == 2) ? w2 : w3;
    int n0 = blockIdx.x * 32, k0 = blockIdx.y * 32;
    #pragma unroll
    for (int i = 0; i < 4; i++) {
        int k = threadIdx.y + i * 8;
        t[k][threadIdx.x] = W[(size_t)(k0 + k) * EMB + n0 + threadIdx.x];
    }
    __syncthreads();
    size_t base = (size_t)z * EMB * EMB;
    #pragma unroll
    for (int i = 0; i < 4; i++) {
        int n = threadIdx.y + i * 8;
        float v = t[threadIdx.x][n];
        __half h = __float2half_rn(v);
        size_t o = base + (size_t)(n0 + n) * EMB + k0 + threadIdx.x;
        hi[o] = h;
        lo[o] = __float2half_rn(v - __half2float(h));
    }
}

// ---------------------------------------------------------------------------
// fp16x2 (Markidis) mma.sync GEMM: C = Ah @ (Wh + Wl) + bias
// A fp16 [M][K]; W hi/lo fp16 [N][K]. 128x128 CTA tile, BK=64,
// 3-stage cp.async pipeline, 8 warps (2x4), warp tile 64x32.
// ---------------------------------------------------------------------------
#define BKC        64
#define TILE_HB    16384              // 128 rows x 128 B
#define STAGE_HB   (3 * TILE_HB)      // Ah, Bh, Bl
#define NCHUNK     (EMB / BKC)        // 16
#define GEMM_SMEM  (3 * STAGE_HB)     // 147456

__device__ __forceinline__ void load_stage(
    unsigned st, int tid, int m0, int n0, int k0,
    const __half* Ah, const __half* Bh, const __half* Bl)
{
    #pragma unroll
    for (int i = 0; i < 4; i++) {
        int idx = tid + i * 256;
        int r   = idx >> 3;
        int s   = idx & 7;
        unsigned sw = swz(r, s);
        size_t ga = (size_t)(m0 + r) * EMB + k0 + s * 8;
        size_t gb = (size_t)(n0 + r) * EMB + k0 + s * 8;
        cp16(st + sw,               Ah + ga);
        cp16(st + TILE_HB + sw,     Bh + gb);
        cp16(st + 2 * TILE_HB + sw, Bl + gb);
    }
}

template<bool SPLIT>
__global__ __launch_bounds__(256) void gemm_mma(
    const __half* __restrict__ Ahi,
    const __half* __restrict__ Whi, const __half* __restrict__ Wlo,
    const float* __restrict__ b0, const float* __restrict__ b1, const float* __restrict__ b2,
    float* __restrict__ Cf0, float* __restrict__ Cf1, float* __restrict__ Cf2,
    __half* __restrict__ Ch0, __half* __restrict__ Cl0,
    __half* __restrict__ Ch1, __half* __restrict__ Cl1,
    __half* __restrict__ Ch2, __half* __restrict__ Cl2,
    float s0, float s1, float s2)
{
    extern __shared__ char smc[];
    const int z = blockIdx.z;
    const float* bias = (z == 0) ? b0 : (z == 1) ? b1 : b2;
    float* Cf  = (z == 0) ? Cf0 : (z == 1) ? Cf1 : Cf2;
    __half* Ch = (z == 0) ? Ch0 : (z == 1) ? Ch1 : Ch2;
    __half* Cl = (z == 0) ? Cl0 : (z == 1) ? Cl1 : Cl2;
    float scale = (z == 0) ? s0 : (z == 1) ? s1 : s2;
    const __half* Bh = Whi + (size_t)z * EMB * EMB;
    const __half* Bl = Wlo + (size_t)z * EMB * EMB;
    const int m0  = blockIdx.y * 128;
    const int n0  = blockIdx.x * 128;
    const int tid = threadIdx.x;
    const int wid = tid >> 5, lane = tid & 31;
    const int wm  = wid & 1;
    const int wn  = wid >> 1;
    const unsigned sb = s2u(smc);

    float acc[4][4][4];
    #pragma unroll
    for (int mt = 0; mt < 4; mt++)
        #pragma unroll
        for (int nt = 0; nt < 4; nt++)
            #pragma unroll
            for (int e = 0; e < 4; e++) acc[mt][nt][e] = 0.0f;

    load_stage(sb,                tid, m0, n0, 0,       Ahi, Bh, Bl);
    CPA_COMMIT();
    load_stage(sb + STAGE_HB,     tid, m0, n0, BKC,     Ahi, Bh, Bl);
    CPA_COMMIT();
    load_stage(sb + 2 * STAGE_HB, tid, m0, n0, 2 * BKC, Ahi, Bh, Bl);
    CPA_COMMIT();

    // ldmatrix lane addressing
    const int arow  = wm * 64 + (lane & 15);          // + mt*16
    const int aseg  = lane >> 4;
    const int brow4 = wn * 32 + ((lane >> 4) << 3) + (lane & 7);  // + nth*16
    const int bseg  = (lane >> 3) & 1;

    for (int c = 0; c < NCHUNK; c++) {
        unsigned st = sb + (unsigned)(c % 3) * STAGE_HB;
        CPA_WAIT2();
        __syncthreads();

        #pragma unroll
        for (int k8 = 0; k8 < 8; k8 += 2) {
            unsigned bh[4][2], bl[4][2];
            #pragma unroll
            for (int nth = 0; nth < 2; nth++) {
                unsigned off = swz(brow4 + nth * 16, k8 + bseg);
                unsigned t4[4];
                ldsm4(t4, st + TILE_HB + off);
                bh[2 * nth][0] = t4[0]; bh[2 * nth][1] = t4[1];
                bh[2 * nth + 1][0] = t4[2]; bh[2 * nth + 1][1] = t4[3];
                ldsm4(t4, st + 2 * TILE_HB + off);
                bl[2 * nth][0] = t4[0]; bl[2 * nth][1] = t4[1];
                bl[2 * nth + 1][0] = t4[2]; bl[2 * nth + 1][1] = t4[3];
            }
            #pragma unroll
            for (int mt = 0; mt < 4; mt++) {
                unsigned off = swz(arow + mt * 16, k8 + aseg);
                unsigned ah[4];
                ldsm4(ah, st + off);
                #pragma unroll
                for (int nt = 0; nt < 4; nt++)
                    mma16816(acc[mt][nt], ah, bh[nt]);
                #pragma unroll
                for (int nt = 0; nt < 4; nt++)
                    mma16816(acc[mt][nt], ah, bl[nt]);
            }
        }
        __syncthreads();
        int cn = c + 3;
        if (cn < NCHUNK) {
            load_stage(st, tid, m0, n0, cn * BKC, Ahi, Bh, Bl);
            CPA_COMMIT();
        }
    }

    #pragma unroll
    for (int mt = 0; mt < 4; mt++) {
        int rbase = m0 + wm * 64 + mt * 16 + (lane >> 2);
        #pragma unroll
        for (int nt = 0; nt < 4; nt++) {
            int col = n0 + wn * 32 + nt * 8 + 2 * (lane & 3);
            float2 bv = *reinterpret_cast<const float2*>(&bias[col]);
            float v0 = acc[mt][nt][0] + bv.x;
            float v1 = acc[mt][nt][1] + bv.y;
            float v2 = acc[mt][nt][2] + bv.x;
            float v3 = acc[mt][nt][3] + bv.y;
            if (SPLIT) {
                v0 *= scale; v1 *= scale; v2 *= scale; v3 *= scale;
                unsigned lo0, lo1;
                unsigned h0 = packsplit(v0, v1, &lo0);
                unsigned h1 = packsplit(v2, v3, &lo1);
                *reinterpret_cast<unsigned*>(&Ch[(size_t)rbase * EMB + col]) = h0;
                *reinterpret_cast<unsigned*>(&Cl[(size_t)rbase * EMB + col]) = lo0;
                *reinterpret_cast<unsigned*>(&Ch[(size_t)(rbase + 8) * EMB + col]) = h1;
                *reinterpret_cast<unsigned*>(&Cl[(size_t)(rbase + 8) * EMB + col]) = lo1;
            } else {
                float2 o0 = {v0, v1}, o1 = {v2, v3};
                *reinterpret_cast<float2*>(&Cf[(size_t)rbase * EMB + col]) = o0;
                *reinterpret_cast<float2*>(&Cf[(size_t)(rbase + 8) * EMB + col]) = o1;
            }
        }
    }
}

// ---------------------------------------------------------------------------
// Tensor-core windowed attention (fp16 2-pass compensated, flash-style)
// S = Qh*(Kh+Kl); O = Ph*(Vh+Vl). Q pre-scaled by log2(e)/32 -> exp2.
// Grid (SEQ/64, HEADS, BATCH), 128 threads, double-buffered cp.async K/V.
// ---------------------------------------------------------------------------
#define KV_TILE   8192                 // 64 rows x 128 B
#define KV_STAGE  (4 * KV_TILE)        // Khi, Klo, Vhi, Vlo
#define ATTN_SMEM (KV_TILE + 2 * KV_STAGE)   // Q hi + 2 stages = 73728

__device__ __forceinline__ void load_kv(
    unsigned st, int tid, int b, int kt, int h,
    const __half* Kh, const __half* Kl, const __half* Vh, const __half* Vl)
{
    #pragma unroll
    for (int i = 0; i < 4; i++) {
        int idx = tid + i * 128;
        int r = idx >> 3, s = idx & 7;
        unsigned sw = swz(r, s);
        size_t g = (size_t)(b * SEQ + kt + r) * EMB + h * DHEAD + s * 8;
        cp16(st + sw,               Kh + g);
        cp16(st + KV_TILE + sw,     Kl + g);
        cp16(st + 2 * KV_TILE + sw, Vh + g);
        cp16(st + 3 * KV_TILE + sw, Vl + g);
    }
}

__global__ __launch_bounds__(128) void attn_mma(
    const __half* __restrict__ Qh,
    const __half* __restrict__ Kh, const __half* __restrict__ Kl,
    const __half* __restrict__ Vh, const __half* __restrict__ Vl,
    __half* __restrict__ Ohi)
{
    extern __shared__ char smb[];
    const unsigned sb = s2u(smb);
    const unsigned Qhi_s = sb;
    const unsigned st0   = sb + KV_TILE;

    const int tid = threadIdx.x, wid = tid >> 5, lane = tid & 31;
    const int q0 = blockIdx.x * 64, h = blockIdx.y, b = blockIdx.z;

    int kstart = q0 - 128; if (kstart < 0) kstart = 0;
    int kend   = q0 + 192; if (kend > SEQ) kend = SEQ;
    const int ntiles = (kend - kstart) >> 6;   // 3..5

    // Prologue: Q tile + first two K/V stages
    {
        const size_t qg = (size_t)(b * SEQ + q0) * EMB + h * DHEAD;
        #pragma unroll
        for (int i = 0; i < 4; i++) {
            int idx = tid + i * 128;
            int r = idx >> 3, s = idx & 7;
            cp16(Qhi_s + swz(r, s), Qh + qg + (size_t)r * EMB + s * 8);
        }
    }
    CPA_COMMIT();
    load_kv(st0,            tid, b, kstart,      h, Kh, Kl, Vh, Vl);
    CPA_COMMIT();
    load_kv(st0 + KV_STAGE, tid, b, kstart + 64, h, Kh, Kl, Vh, Vl);
    CPA_COMMIT();

    CPA_WAIT2();
    __syncthreads();

    // Q fragments into registers
    unsigned qfh[4][4];
    {
        int qrow = wid * 16 + (lane & 15);
        int aks  = lane >> 4;
        #pragma unroll
        for (int kc = 0; kc < 4; kc++)
            ldsm4(qfh[kc], Qhi_s + swz(qrow, kc * 2 + aks));
    }

    float o[8][4];
    #pragma unroll
    for (int i = 0; i < 8; i++)
        #pragma unroll
        for (int e = 0; e < 4; e++) o[i][e] = 0.0f;
    float m0 = -1e30f, m1 = -1e30f, l0 = 0.0f, l1 = 0.0f;

    for (int t = 0; t < ntiles; t++) {
        unsigned st = st0 + (unsigned)(t & 1) * KV_STAGE;
        CPA_WAIT1();
        __syncthreads();
        const int kt = kstart + t * 64;

        // ---- S = Q (Kh + Kl)^T ----
        float s[8][4];
        #pragma unroll
        for (int i = 0; i < 8; i++)
            #pragma unroll
            for (int e = 0; e < 4; e++) s[i][e] = 0.0f;

        #pragma unroll
        for (int np = 0; np < 4; np++) {
            int krow = np * 16 + ((lane >> 4) << 3) + (lane & 7);
            #pragma unroll
            for (int kc = 0; kc < 4; kc++) {
                unsigned off = swz(krow, kc * 2 + ((lane >> 3) & 1));
                unsigned kb[4], kbl[4];
                ldsm4(kb,  st + off);
                ldsm4(kbl, st + KV_TILE + off);
                mma16816(s[2 * np],     qfh[kc], kb);
                mma16816(s[2 * np],     qfh[kc], kbl);
                mma16816(s[2 * np + 1], qfh[kc], kb + 2);
                mma16816(s[2 * np + 1], qfh[kc], kbl + 2);
            }
        }

        // ---- window mask (only edge tiles) ----
        if (kt == q0 + 128 || kt + 128 == q0) {
            int iqb = q0 + wid * 16 + (lane >> 2);
            int jkb = kt + 2 * (lane & 3);
            #pragma unroll
            for (int nt = 0; nt < 8; nt++)
                #pragma unroll
                for (int e = 0; e < 4; e++) {
                    int iq = iqb + ((e >> 1) << 3);
                    int jk = jkb + nt * 8 + (e & 1);
                    int d = iq - jk; if (d < 0) d = -d;
                    if (d > WINDOW) s[nt][e] = -1e30f;
                }
        }

        // ---- online softmax ----
        float mx0 = -1e30f, mx1 = -1e30f;
        #pragma unroll
        for (int nt = 0; nt < 8; nt++) {
            mx0 = fmaxf(mx0, fmaxf(s[nt][0], s[nt][1]));
            mx1 = fmaxf(mx1, fmaxf(s[nt][2], s[nt][3]));
        }
        mx0 = fmaxf(mx0, __shfl_xor_sync(0xffffffffu, mx0, 1));
        mx0 = fmaxf(mx0, __shfl_xor_sync(0xffffffffu, mx0, 2));
        mx1 = fmaxf(mx1, __shfl_xor_sync(0xffffffffu, mx1, 1));
        mx1 = fmaxf(mx1, __shfl_xor_sync(0xffffffffu, mx1, 2));
        float nm0 = fmaxf(m0, mx0), nm1 = fmaxf(m1, mx1);
        float c0 = exp2f(m0 - nm0), c1 = exp2f(m1 - nm1);
        m0 = nm0; m1 = nm1;
        l0 *= c0;  l1 *= c1;
        #pragma unroll
        for (int nt = 0; nt < 8; nt++) {
            o[nt][0] *= c0; o[nt][1] *= c0;
            o[nt][2] *= c1; o[nt][3] *= c1;
        }

        // p = exp2(s - m), pack into A-fragments
        unsigned pha[4][4];
        #pragma unroll
        for (int np = 0; np < 4; np++) {
            float pe0 = exp2f(s[2 * np][0] - m0), pe1 = exp2f(s[2 * np][1] - m0);
            float pe2 = exp2f(s[2 * np][2] - m1), pe3 = exp2f(s[2 * np][3] - m1);
            float po0 = exp2f(s[2 * np + 1][0] - m0), po1 = exp2f(s[2 * np + 1][1] - m0);
            float po2 = exp2f(s[2 * np + 1][2] - m1), po3 = exp2f(s[2 * np + 1][3] - m1);
            l0 += pe0 + pe1 + po0 + po1;
            l1 += pe2 + pe3 + po2 + po3;
            pha[np][0] = pack2h(pe0, pe1);
            pha[np][1] = pack2h(pe2, pe3);
            pha[np][2] = pack2h(po0, po1);
            pha[np][3] = pack2h(po2, po3);
        }

        // ---- O += P (Vh + Vl) ----
        #pragma unroll
        for (int kc2 = 0; kc2 < 4; kc2++) {
            int vrow = kc2 * 16 + (lane & 15);
            #pragma unroll
            for (int dp = 0; dp < 4; dp++) {
                unsigned off = swz(vrow, dp * 2 + (lane >> 4));
                unsigned vb[4], vbl[4];
                ldsm4t(vb,  st + 2 * KV_TILE + off);
                ldsm4t(vbl, st + 3 * KV_TILE + off);
                mma16816(o[2 * dp],     pha[kc2], vb);
                mma16816(o[2 * dp],     pha[kc2], vbl);
                mma16816(o[2 * dp + 1], pha[kc2], vb + 2);
                mma16816(o[2 * dp + 1], pha[kc2], vbl + 2);
            }
        }

        __syncthreads();
        int tn = t + 2;
        if (tn < ntiles) {
            load_kv(st, tid, b, kstart + tn * 64, h, Kh, Kl, Vh, Vl);
        }
        CPA_COMMIT();
    }

    // final normalize + fp16 write
    l0 += __shfl_xor_sync(0xffffffffu, l0, 1);
    l0 += __shfl_xor_sync(0xffffffffu, l0, 2);
    l1 += __shfl_xor_sync(0xffffffffu, l1, 1);
    l1 += __shfl_xor_sync(0xffffffffu, l1, 2);
    float inv0 = 1.0f / l0, inv1 = 1.0f / l1;

    int row0 = q0 + wid * 16 + (lane >> 2);
    size_t t0 = (size_t)(b * SEQ + row0) * EMB + h * DHEAD;
    size_t t1 = t0 + (size_t)8 * EMB;
    #pragma unroll
    for (int nt = 0; nt < 8; nt++) {
        int col = nt * 8 + 2 * (lane & 3);
        *reinterpret_cast<unsigned*>(&Ohi[t0 + col]) = pack2h(o[nt][0] * inv0, o[nt][1] * inv0);
        *reinterpret_cast<unsigned*>(&Ohi[t1 + col]) = pack2h(o[nt][2] * inv1, o[nt][3] * inv1);
    }
}

// ---------------------------------------------------------------------------
// Launch
// ---------------------------------------------------------------------------
extern "C" void kernel_launch(void* const* d_in, const int* in_sizes, int n_in,
                              void* d_out, int out_size)
{
    const float* x  = (const float*)d_in[0];
    const float* wq = (const float*)d_in[1];
    const float* bq = (const float*)d_in[2];
    const float* wk = (const float*)d_in[3];
    const float* bk = (const float*)d_in[4];
    const float* wv = (const float*)d_in[5];
    const float* bv = (const float*)d_in[6];
    const float* wo = (const float*)d_in[7];
    const float* bo = (const float*)d_in[8];
    float* out = (float*)d_out;

    __half *xhi, *qhi, *qlo, *khi, *klo, *vhi, *vlo, *ahi, *whi, *wlo;
    cudaGetSymbolAddress((void**)&xhi, g_xhi);
    cudaGetSymbolAddress((void**)&qhi, g_qhi);
    cudaGetSymbolAddress((void**)&qlo, g_qlo);
    cudaGetSymbolAddress((void**)&khi, g_khi);
    cudaGetSymbolAddress((void**)&klo, g_klo);
    cudaGetSymbolAddress((void**)&vhi, g_vhi);
    cudaGetSymbolAddress((void**)&vlo, g_vlo);
    cudaGetSymbolAddress((void**)&ahi, g_ahi);
    cudaGetSymbolAddress((void**)&whi, g_whi);
    cudaGetSymbolAddress((void**)&wlo, g_wlo);

    cudaFuncSetAttribute(gemm_mma<true>,  cudaFuncAttributeMaxDynamicSharedMemorySize, GEMM_SMEM);
    cudaFuncSetAttribute(gemm_mma<false>, cudaFuncAttributeMaxDynamicSharedMemorySize, GEMM_SMEM);
    cudaFuncSetAttribute(attn_mma, cudaFuncAttributeMaxDynamicSharedMemorySize, ATTN_SMEM);

    const int n4 = MTOT * EMB / 4;

    // 1) conversions
    tohalf_kernel<<<n4 / 256, 256>>>(x, xhi, n4);
    wsplit_kernel<<<dim3(32, 32, 4), dim3(32, 8)>>>(wq, wk, wv, wo, whi, wlo);

    // 2) QKV projections -> hi/lo fp16 (Q pre-scaled by log2e/32)
    gemm_mma<true><<<dim3(8, 32, 3), 256, GEMM_SMEM>>>(
        xhi, whi, wlo, bq, bk, bv,
        nullptr, nullptr, nullptr,
        qhi, qlo, khi, klo, vhi, vlo,
        QSCALE, 1.0f, 1.0f);

    // 3) Tensor-core windowed attention -> fp16
    attn_mma<<<dim3(SEQ / 64, HEADS, BATCH), 128, ATTN_SMEM>>>(
        qhi, khi, klo, vhi, vlo, ahi);

    // 4) Output projection -> fp32
    gemm_mma<false><<<dim3(8, 32, 1), 256, GEMM_SMEM>>>(
        ahi, whi + (size_t)3 * EMB * EMB, wlo + (size_t)3 * EMB * EMB,
        bo, bo, bo,
        out, out, out,
        nullptr, nullptr, nullptr, nullptr, nullptr, nullptr,
        1.0f, 1.0f, 1.0f);
}